// round 14
// baseline (speedup 1.0000x reference)
#include <cuda_runtime.h>
#include <cuda_fp16.h>
#include <cstdint>

#define BB 16
#define NN 16384
#define CC 128
#define KK 9
#define TM 128
#define THREADS 256
#define NCHUNK_CONV 72          // 8 c8 * 9 ko, K=16 each
#define NCHUNK 80               // + 8 skip chunks
#define CHUNK_GB 4096           // bytes per W chunk in global
#define ROW_SB 48               // smem row stride (32B data + 16B pad)
#define BUF_B (128 * ROW_SB)    // 6144
#define NBUF 4

// smem layout (bytes)
#define WBUF_OFF 0                          // 4 * 6144 = 24576
#define P2_OFF   (NBUF * BUF_B)             // 24576, 128*108*4 = 55296
#define IDX_OFF  (P2_OFF + 55296)           // 79872, 128*9*4 = 4608
#define BIAS_OFF (IDX_OFF + 4608)           // 84480, 256*4
#define SMEM_TOTAL (BIAS_OFF + 1024)        // 85504

// W pre-permuted fp16: [chunk][o(128)][p(16)]
__device__ __align__(16) __half g_Wc[NCHUNK_CONV * 2048];
__device__ __align__(16) __half g_Ws[8 * 2048];

// position p -> channel-within-16 (lane's 4 frag k-values = contiguous float4)
__host__ __device__ __forceinline__ int perm16(int p) {
    int e = p & 1;
    return (p < 8) ? ((p >> 1) * 4 + e) : (((p - 8) >> 1) * 4 + 2 + e);
}

__global__ void prep_w(const float* __restrict__ Wc, const float* __restrict__ Ws) {
    int t = blockIdx.x * blockDim.x + threadIdx.x;
    if (t < NCHUNK_CONV * 2048) {
        int q = t >> 11, r = t & 2047, o = r >> 4, p = r & 15;
        int c8 = q / 9, ko = q % 9;
        g_Wc[t] = __float2half_rn(Wc[o * 1152 + ko * CC + c8 * 16 + perm16(p)]);
    }
    if (t < 8 * 2048) {
        int q = t >> 11, r = t & 2047, o = r >> 4, p = r & 15;
        g_Ws[t] = __float2half_rn(Ws[o * CC + q * 16 + perm16(p)]);
    }
}

// ---------------- PTX helpers ----------------
__device__ __forceinline__ uint32_t smem_u32(const void* p) {
    uint32_t a;
    asm("{ .reg .u64 t; cvta.to.shared.u64 t, %1; cvt.u32.u64 %0, t; }" : "=r"(a) : "l"(p));
    return a;
}
#define CP_ASYNC16(dst, src) \
    asm volatile("cp.async.cg.shared.global [%0], [%1], 16;" :: "r"(dst), "l"(src))
#define CP_COMMIT() asm volatile("cp.async.commit_group;" ::: "memory")
#define CP_WAIT(n)  asm volatile("cp.async.wait_group %0;" :: "n"(n) : "memory")

__device__ __forceinline__ void ldsm_x4(uint32_t* r, uint32_t addr) {
    asm volatile("ldmatrix.sync.aligned.m8n8.x4.shared.b16 {%0,%1,%2,%3}, [%4];"
                 : "=r"(r[0]), "=r"(r[1]), "=r"(r[2]), "=r"(r[3]) : "r"(addr));
}
__device__ __forceinline__ void mma16816(float* c, const uint32_t* a,
                                         uint32_t b0, uint32_t b1) {
    asm volatile("mma.sync.aligned.m16n8k16.row.col.f32.f16.f16.f32 "
                 "{%0,%1,%2,%3}, {%4,%5,%6,%7}, {%8,%9}, {%0,%1,%2,%3};"
                 : "+f"(c[0]), "+f"(c[1]), "+f"(c[2]), "+f"(c[3])
                 : "r"(a[0]), "r"(a[1]), "r"(a[2]), "r"(a[3]), "r"(b0), "r"(b1));
}
__device__ __forceinline__ float elu(float v) {
    float e;
    asm("ex2.approx.f32 %0, %1;" : "=f"(e) : "f"(v * 1.44269504f));
    return v > 0.f ? v : e - 1.f;
}
__device__ __forceinline__ void fma4(float4& a, float s, const float4& v) {
    a.x = fmaf(s, v.x, a.x); a.y = fmaf(s, v.y, a.y);
    a.z = fmaf(s, v.z, a.z); a.w = fmaf(s, v.w, a.w);
}
__device__ __forceinline__ uint32_t h2pack(float a, float b) {
    __half2 h = __floats2half2_rn(a, b);
    return *reinterpret_cast<uint32_t*>(&h);
}

// cooperative chunk fetch (R6-exact): 256 threads, ONE 16B each = 4KB chunk
__device__ __forceinline__ void issue_chunk(uint32_t wbase, int i, int tid) {
    const char* src = (i < NCHUNK_CONV)
        ? (const char*)g_Wc + (size_t)i * CHUNK_GB
        : (const char*)g_Ws + (size_t)(i - NCHUNK_CONV) * CHUNK_GB;
    int o = tid >> 1, h = tid & 1;
    uint32_t dst = wbase + (i & (NBUF - 1)) * BUF_B + o * ROW_SB + h * 16;
    CP_ASYNC16(dst, src + o * 32 + h * 16);
    CP_COMMIT();
}

__global__ __launch_bounds__(THREADS, 1)
void paiconv_rp(const float* __restrict__ x, const int* __restrict__ idxg,
                const float* __restrict__ P, const float* __restrict__ b_conv,
                const float* __restrict__ b_skip, float* __restrict__ out)
{
    extern __shared__ char smem[];
    const uint32_t sb = smem_u32(smem);
    const int tid  = threadIdx.x;
    const int lane = tid & 31;
    const int wid  = tid >> 5;
    const int n0   = blockIdx.x * TM;
    const int b    = blockIdx.y;

    float* s_P2   = (float*)(smem + P2_OFF);     // [node][ko][12]
    int*   s_idx  = (int*)(smem + IDX_OFF);
    float* s_bias = (float*)(smem + BIAS_OFF);

    // start W pipeline immediately
    issue_chunk(sb + WBUF_OFF, 0, tid);
    issue_chunk(sb + WBUF_OFF, 1, tid);
    issue_chunk(sb + WBUF_OFF, 2, tid);

    // stage P (padded [node][ko][12]), idx, bias
    for (int t = tid; t < TM * 81; t += THREADS) {
        int node = t / 81;
        int rem = t - node * 81;
        int ko = rem / 9, j = rem - ko * 9;
        s_P2[node * 108 + ko * 12 + j] = P[(size_t)n0 * 81 + t];
    }
    for (int t = tid; t < TM * KK; t += THREADS) s_idx[t] = idxg[n0 * KK + t];
    if (tid < CC) { s_bias[tid] = b_conv[tid]; s_bias[CC + tid] = b_skip[tid]; }
    __syncthreads();

    const float* xb = x + (size_t)b * NN * CC;

    // lane-owned rows within warp m16 tile
    const int r0l = wid * 16 + (lane >> 2);      // local node 0..127
    const int r1l = r0l + 8;
    const int q4  = (lane & 3) * 16;             // byte offset of lane's float4

    int idxr[2][KK];
    #pragma unroll
    for (int j = 0; j < KK; j++) {
        idxr[0][j] = s_idx[r0l * KK + j];
        idxr[1][j] = s_idx[r1l * KK + j];
    }

    float acc[64];
    #pragma unroll
    for (int i = 0; i < 64; i++) acc[i] = 0.f;

    float4 xg[2][KK];
    const uint32_t ldsm_base = sb + WBUF_OFF + (lane & 15) * ROW_SB + (lane >> 4) * 16;

    // ---- prologue: gather slice 0, compute a_cur = mix(chunk 0) ----
    #pragma unroll
    for (int rr = 0; rr < 2; rr++)
        #pragma unroll
        for (int j = 0; j < KK; j++) {
            int ix = idxr[rr][j];
            float4 v = make_float4(0.f, 0.f, 0.f, 0.f);
            if ((unsigned)ix < (unsigned)NN)
                v = __ldg((const float4*)((const char*)xb + (size_t)ix * 512 + q4));
            xg[rr][j] = v;
        }

    uint32_t a_cur[4];
    {
        const float* p0 = s_P2 + r0l * 108;
        const float* p1 = s_P2 + r1l * 108;
        float4 pa0 = *(const float4*)p0, pb0 = *(const float4*)(p0 + 4);
        float4 pa1 = *(const float4*)p1, pb1 = *(const float4*)(p1 + 4);
        float4 v0 = make_float4(0.f, 0.f, 0.f, 0.f);
        float4 v1 = make_float4(0.f, 0.f, 0.f, 0.f);
        fma4(v0, pa0.x, xg[0][0]); fma4(v1, pa1.x, xg[1][0]);
        fma4(v0, pa0.y, xg[0][1]); fma4(v1, pa1.y, xg[1][1]);
        fma4(v0, pa0.z, xg[0][2]); fma4(v1, pa1.z, xg[1][2]);
        fma4(v0, pa0.w, xg[0][3]); fma4(v1, pa1.w, xg[1][3]);
        fma4(v0, pb0.x, xg[0][4]); fma4(v1, pb1.x, xg[1][4]);
        fma4(v0, pb0.y, xg[0][5]); fma4(v1, pb1.y, xg[1][5]);
        fma4(v0, pb0.z, xg[0][6]); fma4(v1, pb1.z, xg[1][6]);
        fma4(v0, pb0.w, xg[0][7]); fma4(v1, pb1.w, xg[1][7]);
        fma4(v0, p0[8], xg[0][8]); fma4(v1, p1[8], xg[1][8]);
        a_cur[0] = h2pack(elu(v0.x), elu(v0.y));
        a_cur[1] = h2pack(elu(v1.x), elu(v1.y));
        a_cur[2] = h2pack(elu(v0.z), elu(v0.w));
        a_cur[3] = h2pack(elu(v1.z), elu(v1.w));
    }

    int komix = 1, c8mix = 0;                    // state for next mix = chunk 1

    for (int ci = 0; ci < NCHUNK; ci++) {
        if (ci < 77) { CP_WAIT(2); } else if (ci == 77) { CP_WAIT(1); } else { CP_WAIT(0); }
        __syncthreads();
        if (ci + 3 < NCHUNK) issue_chunk(sb + WBUF_OFF, ci + 3, tid);

        // fold conv accs once, before chunk 72's MMAs
        if (ci == NCHUNK_CONV) {
            const int cbase = (lane & 3) * 2;
            #pragma unroll
            for (int t = 0; t < 16; t++) {
                int col = t * 8 + cbase;
                float2 bc  = *(const float2*)(s_bias + col);
                float2 bs2 = *(const float2*)(s_bias + 128 + col);
                acc[t * 4 + 0] = elu(acc[t * 4 + 0] + bc.x) + bs2.x;
                acc[t * 4 + 1] = elu(acc[t * 4 + 1] + bc.y) + bs2.y;
                acc[t * 4 + 2] = elu(acc[t * 4 + 2] + bc.x) + bs2.x;
                acc[t * 4 + 3] = elu(acc[t * 4 + 3] + bc.y) + bs2.y;
            }
        }

        // ---- B fragments for chunk ci ----
        const uint32_t wb = ldsm_base + (ci & (NBUF - 1)) * BUF_B;
        uint32_t bf[8][4];
        #pragma unroll
        for (int g = 0; g < 8; g++)
            ldsm_x4(bf[g], wb + g * 16 * ROW_SB);

        // ---- a_next = mix/load for chunk ci+1 (independent of the MMAs below) ----
        uint32_t a_next[4];
        const int mi = ci + 1;
        if (mi < NCHUNK_CONV) {
            if (komix == 0) {
                #pragma unroll
                for (int rr = 0; rr < 2; rr++)
                    #pragma unroll
                    for (int j = 0; j < KK; j++) {
                        int ix = idxr[rr][j];
                        float4 v = make_float4(0.f, 0.f, 0.f, 0.f);
                        if ((unsigned)ix < (unsigned)NN)
                            v = __ldg((const float4*)((const char*)xb + (size_t)ix * 512 + c8mix * 64 + q4));
                        xg[rr][j] = v;
                    }
            }
            const float* p0 = s_P2 + r0l * 108 + komix * 12;
            const float* p1 = s_P2 + r1l * 108 + komix * 12;
            float4 pa0 = *(const float4*)p0, pb0 = *(const float4*)(p0 + 4);
            float4 pa1 = *(const float4*)p1, pb1 = *(const float4*)(p1 + 4);
            float4 v0 = make_float4(0.f, 0.f, 0.f, 0.f);
            float4 v1 = make_float4(0.f, 0.f, 0.f, 0.f);
            fma4(v0, pa0.x, xg[0][0]); fma4(v1, pa1.x, xg[1][0]);
            fma4(v0, pa0.y, xg[0][1]); fma4(v1, pa1.y, xg[1][1]);
            fma4(v0, pa0.z, xg[0][2]); fma4(v1, pa1.z, xg[1][2]);
            fma4(v0, pa0.w, xg[0][3]); fma4(v1, pa1.w, xg[1][3]);
            fma4(v0, pb0.x, xg[0][4]); fma4(v1, pb1.x, xg[1][4]);
            fma4(v0, pb0.y, xg[0][5]); fma4(v1, pb1.y, xg[1][5]);
            fma4(v0, pb0.z, xg[0][6]); fma4(v1, pb1.z, xg[1][6]);
            fma4(v0, pb0.w, xg[0][7]); fma4(v1, pb1.w, xg[1][7]);
            fma4(v0, p0[8], xg[0][8]); fma4(v1, p1[8], xg[1][8]);
            a_next[0] = h2pack(elu(v0.x), elu(v0.y));
            a_next[1] = h2pack(elu(v1.x), elu(v1.y));
            a_next[2] = h2pack(elu(v0.z), elu(v0.w));
            a_next[3] = h2pack(elu(v1.z), elu(v1.w));
            if (++komix == 9) { komix = 0; c8mix++; }
        } else if (mi < NCHUNK) {
            int c8s = mi - NCHUNK_CONV;
            float4 v0 = __ldg((const float4*)((const char*)xb + (size_t)(n0 + r0l) * 512 + c8s * 64 + q4));
            float4 v1 = __ldg((const float4*)((const char*)xb + (size_t)(n0 + r1l) * 512 + c8s * 64 + q4));
            a_next[0] = h2pack(v0.x, v0.y);
            a_next[1] = h2pack(v1.x, v1.y);
            a_next[2] = h2pack(v0.z, v0.w);
            a_next[3] = h2pack(v1.z, v1.w);
        }

        // ---- MMAs for chunk ci (tensor stream; interleaves with mix above) ----
        #pragma unroll
        for (int g = 0; g < 8; g++) {
            mma16816(acc + (2 * g) * 4,     a_cur, bf[g][0], bf[g][2]);
            mma16816(acc + (2 * g + 1) * 4, a_cur, bf[g][1], bf[g][3]);
        }

        a_cur[0] = a_next[0]; a_cur[1] = a_next[1];
        a_cur[2] = a_next[2]; a_cur[3] = a_next[3];
    }

    // ---------------- epilogue: store ----------------
    {
        const int cbase = (lane & 3) * 2;
        float* o0 = out + ((size_t)b * NN + n0 + r0l) * CC + cbase;
        float* o1 = out + ((size_t)b * NN + n0 + r1l) * CC + cbase;
        #pragma unroll
        for (int t = 0; t < 16; t++) {
            *(float2*)(o0 + t * 8) = make_float2(acc[t * 4 + 0], acc[t * 4 + 1]);
            *(float2*)(o1 + t * 8) = make_float2(acc[t * 4 + 2], acc[t * 4 + 3]);
        }
    }
}

extern "C" void kernel_launch(void* const* d_in, const int* in_sizes, int n_in,
                              void* d_out, int out_size) {
    const float* x       = (const float*)d_in[0];
    const int*   indices = (const int*)  d_in[1];
    const float* P       = (const float*)d_in[2];
    const float* W_conv  = (const float*)d_in[3];
    const float* b_conv  = (const float*)d_in[4];
    const float* W_skip  = (const float*)d_in[5];
    const float* b_skip  = (const float*)d_in[6];
    float* out = (float*)d_out;

    prep_w<<<(NCHUNK_CONV * 2048 + 255) / 256, 256>>>(W_conv, W_skip);

    cudaFuncSetAttribute(paiconv_rp,
                         cudaFuncAttributeMaxDynamicSharedMemorySize, SMEM_TOTAL);
    dim3 grid(NN / TM, BB);
    paiconv_rp<<<grid, THREADS, SMEM_TOTAL>>>(x, indices, P, b_conv, b_skip, out);
}

// round 15
// speedup vs baseline: 1.2490x; 1.2490x over previous
#include <cuda_runtime.h>
#include <cuda_fp16.h>
#include <cstdint>

#define BB 16
#define NN 16384
#define CC 128
#define KK 9
#define TM 128
#define THREADS 256
#define NCHUNK_CONV 72          // 8 c8 * 9 ko, K=16 each
#define NCHUNK 80               // + 8 skip chunks
#define NREGION 40              // 2 chunks per region
#define REGION_GB 8192          // bytes per W region in global
#define ROW_SB 80               // smem row stride (64B data + 16B pad)
#define BUF_B (128 * ROW_SB)    // 10240 per region buffer
#define NBUF 4

// smem layout (bytes)
#define WBUF_OFF 0                          // 4 * 10240 = 40960
#define P2_OFF   (NBUF * BUF_B)             // 40960, 128*108*4 = 55296
#define IDX_OFF  (P2_OFF + 55296)           // 96256, 128*9*4 = 4608
#define BIAS_OFF (IDX_OFF + 4608)           // 100864, 256*4
#define SMEM_TOTAL (BIAS_OFF + 1024)        // 101888

// W pre-permuted fp16: [region 40][o 128][k 32] (two perm16'd k16 halves)
__device__ __align__(16) __half g_W2[NREGION * 128 * 32];

// position p -> channel-within-16 (lane's 4 frag k-values = contiguous float4)
__host__ __device__ __forceinline__ int perm16(int p) {
    int e = p & 1;
    return (p < 8) ? ((p >> 1) * 4 + e) : (((p - 8) >> 1) * 4 + 2 + e);
}

__global__ void prep_w(const float* __restrict__ Wc, const float* __restrict__ Ws) {
    int t = blockIdx.x * blockDim.x + threadIdx.x;
    if (t < NREGION * 128 * 32) {
        int rg = t >> 12, rem = t & 4095, o = rem >> 5, kk = rem & 31;
        int ci = rg * 2 + (kk >> 4);
        int p  = kk & 15;
        float v;
        if (ci < NCHUNK_CONV) {
            int c8 = ci / 9, ko = ci % 9;
            v = Wc[o * 1152 + ko * CC + c8 * 16 + perm16(p)];
        } else {
            int cs = ci - NCHUNK_CONV;
            v = Ws[o * CC + cs * 16 + perm16(p)];
        }
        g_W2[t] = __float2half_rn(v);
    }
}

// ---------------- PTX helpers ----------------
__device__ __forceinline__ uint32_t smem_u32(const void* p) {
    uint32_t a;
    asm("{ .reg .u64 t; cvta.to.shared.u64 t, %1; cvt.u32.u64 %0, t; }" : "=r"(a) : "l"(p));
    return a;
}
#define CP_ASYNC16(dst, src) \
    asm volatile("cp.async.cg.shared.global [%0], [%1], 16;" :: "r"(dst), "l"(src))
#define CP_COMMIT() asm volatile("cp.async.commit_group;" ::: "memory")
#define CP_WAIT(n)  asm volatile("cp.async.wait_group %0;" :: "n"(n) : "memory")

__device__ __forceinline__ void ldsm_x4(uint32_t* r, uint32_t addr) {
    asm volatile("ldmatrix.sync.aligned.m8n8.x4.shared.b16 {%0,%1,%2,%3}, [%4];"
                 : "=r"(r[0]), "=r"(r[1]), "=r"(r[2]), "=r"(r[3]) : "r"(addr));
}
__device__ __forceinline__ void mma16816(float* c, const uint32_t* a,
                                         uint32_t b0, uint32_t b1) {
    asm volatile("mma.sync.aligned.m16n8k16.row.col.f32.f16.f16.f32 "
                 "{%0,%1,%2,%3}, {%4,%5,%6,%7}, {%8,%9}, {%0,%1,%2,%3};"
                 : "+f"(c[0]), "+f"(c[1]), "+f"(c[2]), "+f"(c[3])
                 : "r"(a[0]), "r"(a[1]), "r"(a[2]), "r"(a[3]), "r"(b0), "r"(b1));
}
__device__ __forceinline__ float elu(float v) {
    float e;
    asm("ex2.approx.f32 %0, %1;" : "=f"(e) : "f"(v * 1.44269504f));
    return v > 0.f ? v : e - 1.f;
}
__device__ __forceinline__ void fma4(float4& a, float s, const float4& v) {
    a.x = fmaf(s, v.x, a.x); a.y = fmaf(s, v.y, a.y);
    a.z = fmaf(s, v.z, a.z); a.w = fmaf(s, v.w, a.w);
}
__device__ __forceinline__ uint32_t h2pack(float a, float b) {
    __half2 h = __floats2half2_rn(a, b);
    return *reinterpret_cast<uint32_t*>(&h);
}

// region fetch: 8KB, 256 threads x 2 x 16B, ONE commit
__device__ __forceinline__ void issue_region(uint32_t wbase, int rg, int tid) {
    const char* src = (const char*)g_W2 + (size_t)rg * REGION_GB;
    #pragma unroll
    for (int e = 0; e < 2; e++) {
        int id = tid + e * THREADS;            // 0..511
        int o = id >> 2, part = id & 3;        // 4 x 16B per 64B row
        uint32_t dst = wbase + (rg & (NBUF - 1)) * BUF_B + o * ROW_SB + part * 16;
        CP_ASYNC16(dst, src + o * 64 + part * 16);
    }
    CP_COMMIT();
}

__global__ __launch_bounds__(THREADS, 1)
void paiconv_rg(const float* __restrict__ x, const int* __restrict__ idxg,
                const float* __restrict__ P, const float* __restrict__ b_conv,
                const float* __restrict__ b_skip, float* __restrict__ out)
{
    extern __shared__ char smem[];
    const uint32_t sb = smem_u32(smem);
    const int tid  = threadIdx.x;
    const int lane = tid & 31;
    const int wid  = tid >> 5;
    const int n0   = blockIdx.x * TM;
    const int b    = blockIdx.y;

    float* s_P2   = (float*)(smem + P2_OFF);     // [node][ko][12]
    int*   s_idx  = (int*)(smem + IDX_OFF);
    float* s_bias = (float*)(smem + BIAS_OFF);

    // start W pipeline: regions 0,1,2
    issue_region(sb + WBUF_OFF, 0, tid);
    issue_region(sb + WBUF_OFF, 1, tid);
    issue_region(sb + WBUF_OFF, 2, tid);

    // stage P (padded [node][ko][12]), idx, bias
    for (int t = tid; t < TM * 81; t += THREADS) {
        int node = t / 81;
        int rem = t - node * 81;
        int ko = rem / 9, j = rem - ko * 9;
        s_P2[node * 108 + ko * 12 + j] = P[(size_t)n0 * 81 + t];
    }
    for (int t = tid; t < TM * KK; t += THREADS) s_idx[t] = idxg[n0 * KK + t];
    if (tid < CC) { s_bias[tid] = b_conv[tid]; s_bias[CC + tid] = b_skip[tid]; }
    __syncthreads();

    const float* xb = x + (size_t)b * NN * CC;

    // lane-owned rows within warp m16 tile
    const int r0l = wid * 16 + (lane >> 2);      // local node 0..127
    const int r1l = r0l + 8;
    const int q4  = (lane & 3) * 16;             // byte offset of lane's float4

    int idxr[2][KK];
    #pragma unroll
    for (int j = 0; j < KK; j++) {
        idxr[0][j] = s_idx[r0l * KK + j];
        idxr[1][j] = s_idx[r1l * KK + j];
    }

    float acc[64];
    #pragma unroll
    for (int i = 0; i < 64; i++) acc[i] = 0.f;

    float4 xg[2][KK];
    const uint32_t ldsm_base = sb + WBUF_OFF + (lane & 15) * ROW_SB + (lane >> 4) * 16;

    // ---------------- conv: 72 chunks (c8 outer, ko inner) ----------------
    int ci = 0;
    for (int c8 = 0; c8 < 8; c8++) {
        // gather this channel-slice for 2 rows x 9 neighbors (fp32, reused 9x)
        #pragma unroll
        for (int r = 0; r < 2; r++)
            #pragma unroll
            for (int j = 0; j < KK; j++) {
                int ix = idxr[r][j];
                float4 v = make_float4(0.f, 0.f, 0.f, 0.f);
                if ((unsigned)ix < (unsigned)NN)
                    v = __ldg((const float4*)((const char*)xb + (size_t)ix * 512 + c8 * 64 + q4));
                xg[r][j] = v;
            }
        #pragma unroll
        for (int ko = 0; ko < 9; ko++, ci++) {
            if ((ci & 1) == 0) {
                if (ci < 74) { CP_WAIT(2); } else if (ci == 74) { CP_WAIT(1); } else { CP_WAIT(0); }
                __syncthreads();
                int rg = (ci >> 1) + 3;
                if (rg < NREGION) issue_region(sb + WBUF_OFF, rg, tid);
            }

            // mix: v0/v1 = P[row][ko][:] . xg[row][:]  (fp32)
            const float* p0 = s_P2 + r0l * 108 + ko * 12;
            const float* p1 = s_P2 + r1l * 108 + ko * 12;
            float4 v0 = make_float4(0.f, 0.f, 0.f, 0.f);
            float4 v1 = make_float4(0.f, 0.f, 0.f, 0.f);
            float4 pa0 = *(const float4*)p0, pb0 = *(const float4*)(p0 + 4);
            float4 pa1 = *(const float4*)p1, pb1 = *(const float4*)(p1 + 4);
            fma4(v0, pa0.x, xg[0][0]); fma4(v0, pa0.y, xg[0][1]);
            fma4(v0, pa0.z, xg[0][2]); fma4(v0, pa0.w, xg[0][3]);
            fma4(v0, pb0.x, xg[0][4]); fma4(v0, pb0.y, xg[0][5]);
            fma4(v0, pb0.z, xg[0][6]); fma4(v0, pb0.w, xg[0][7]);
            fma4(v0, p0[8], xg[0][8]);
            fma4(v1, pa1.x, xg[1][0]); fma4(v1, pa1.y, xg[1][1]);
            fma4(v1, pa1.z, xg[1][2]); fma4(v1, pa1.w, xg[1][3]);
            fma4(v1, pb1.x, xg[1][4]); fma4(v1, pb1.y, xg[1][5]);
            fma4(v1, pb1.z, xg[1][6]); fma4(v1, pb1.w, xg[1][7]);
            fma4(v1, p1[8], xg[1][8]);

            uint32_t a[4];
            a[0] = h2pack(elu(v0.x), elu(v0.y));
            a[1] = h2pack(elu(v1.x), elu(v1.y));
            a[2] = h2pack(elu(v0.z), elu(v0.w));
            a[3] = h2pack(elu(v1.z), elu(v1.w));

            const uint32_t wb = ldsm_base + ((ci >> 1) & (NBUF - 1)) * BUF_B + (ci & 1) * 32;
            #pragma unroll
            for (int g = 0; g < 8; g++) {
                uint32_t bf[4];
                ldsm_x4(bf, wb + g * 16 * ROW_SB);
                mma16816(acc + (2 * g) * 4,     a, bf[0], bf[2]);
                mma16816(acc + (2 * g + 1) * 4, a, bf[1], bf[3]);
            }
        }
    }

    // ---------------- fold: acc = elu(acc + bc) + bs ----------------
    {
        const int cbase = (lane & 3) * 2;
        #pragma unroll
        for (int t = 0; t < 16; t++) {
            int col = t * 8 + cbase;
            float2 bc  = *(const float2*)(s_bias + col);
            float2 bs2 = *(const float2*)(s_bias + 128 + col);
            acc[t * 4 + 0] = elu(acc[t * 4 + 0] + bc.x) + bs2.x;
            acc[t * 4 + 1] = elu(acc[t * 4 + 1] + bc.y) + bs2.y;
            acc[t * 4 + 2] = elu(acc[t * 4 + 2] + bc.x) + bs2.x;
            acc[t * 4 + 3] = elu(acc[t * 4 + 3] + bc.y) + bs2.y;
        }
    }

    // ---------------- skip: 8 chunks, A = x directly ----------------
    for (int c8 = 0; c8 < 8; c8++, ci++) {
        if ((ci & 1) == 0) {
            if (ci < 74) { CP_WAIT(2); } else if (ci == 74) { CP_WAIT(1); } else { CP_WAIT(0); }
            __syncthreads();
            int rg = (ci >> 1) + 3;
            if (rg < NREGION) issue_region(sb + WBUF_OFF, rg, tid);
        }

        float4 v0 = __ldg((const float4*)((const char*)xb + (size_t)(n0 + r0l) * 512 + c8 * 64 + q4));
        float4 v1 = __ldg((const float4*)((const char*)xb + (size_t)(n0 + r1l) * 512 + c8 * 64 + q4));
        uint32_t a[4];
        a[0] = h2pack(v0.x, v0.y);
        a[1] = h2pack(v1.x, v1.y);
        a[2] = h2pack(v0.z, v0.w);
        a[3] = h2pack(v1.z, v1.w);

        const uint32_t wb = ldsm_base + ((ci >> 1) & (NBUF - 1)) * BUF_B + (ci & 1) * 32;
        #pragma unroll
        for (int g = 0; g < 8; g++) {
            uint32_t bf[4];
            ldsm_x4(bf, wb + g * 16 * ROW_SB);
            mma16816(acc + (2 * g) * 4,     a, bf[0], bf[2]);
            mma16816(acc + (2 * g + 1) * 4, a, bf[1], bf[3]);
        }
    }

    // ---------------- epilogue: store ----------------
    {
        const int cbase = (lane & 3) * 2;
        float* o0 = out + ((size_t)b * NN + n0 + r0l) * CC + cbase;
        float* o1 = out + ((size_t)b * NN + n0 + r1l) * CC + cbase;
        #pragma unroll
        for (int t = 0; t < 16; t++) {
            *(float2*)(o0 + t * 8) = make_float2(acc[t * 4 + 0], acc[t * 4 + 1]);
            *(float2*)(o1 + t * 8) = make_float2(acc[t * 4 + 2], acc[t * 4 + 3]);
        }
    }
}

extern "C" void kernel_launch(void* const* d_in, const int* in_sizes, int n_in,
                              void* d_out, int out_size) {
    const float* x       = (const float*)d_in[0];
    const int*   indices = (const int*)  d_in[1];
    const float* P       = (const float*)d_in[2];
    const float* W_conv  = (const float*)d_in[3];
    const float* b_conv  = (const float*)d_in[4];
    const float* W_skip  = (const float*)d_in[5];
    const float* b_skip  = (const float*)d_in[6];
    float* out = (float*)d_out;

    prep_w<<<(NREGION * 128 * 32 + 255) / 256, 256>>>(W_conv, W_skip);

    cudaFuncSetAttribute(paiconv_rg,
                         cudaFuncAttributeMaxDynamicSharedMemorySize, SMEM_TOTAL);
    dim3 grid(NN / TM, BB);
    paiconv_rg<<<grid, THREADS, SMEM_TOTAL>>>(x, indices, P, b_conv, b_skip, out);
}